// round 15
// baseline (speedup 1.0000x reference)
#include <cuda_runtime.h>
#include <cuda_fp16.h>
#include <math.h>

// Problem constants: N=100000, D=128, E=1600000
#define DD   128
#define EMAX 1600000
#define NB   1184          // 8 blocks/SM * 148 (GB300: 152 SMs -> co-residency holds)
#define TPB  256
#define NTHREADS (NB * TPB)

#define PDL_WAIT()    asm volatile("griddepcontrol.wait;" ::: "memory")
#define PDL_TRIGGER() asm volatile("griddepcontrol.launch_dependents;" ::: "memory")

// Static device scratch (no allocations)
__device__ __half g_srch[100000 * DD];  // fp16 src table (row = 256B = 16 uint4)
__device__ __half g_dsth[100000 * DD];  // fp16 dst table
__device__ float  g_lik[EMAX];          // likelihood (k_edge -> k_post)
__device__ double g_p1[NB], g_p2[NB], g_p3[NB];
__device__ float  g_mu, g_inv;
__device__ volatile float g_im;
__device__ unsigned g_c1, g_c2;         // monotonic arrival counters (replay-safe)
__device__ volatile unsigned g_done;    // monotonic round-completion counter

// ---------------------------------------------------------------------------
// K0: fp32 -> fp16 tables (streaming, unrolled x2; .cg keeps tables L2-hot)
// ---------------------------------------------------------------------------
__global__ __launch_bounds__(TPB) void k_conv(
    const float* __restrict__ src, const float* __restrict__ dst, int total)
{
    const int nt8 = total >> 3;
    const float4* __restrict__ s4 = (const float4*)src;
    const float4* __restrict__ d4 = (const float4*)dst;
    uint4* __restrict__ so = (uint4*)g_srch;
    uint4* __restrict__ dsto = (uint4*)g_dsth;

    const int tid = blockIdx.x * TPB + threadIdx.x;

    for (int i0 = tid; i0 < nt8; i0 += 2 * NTHREADS) {
        const int i1 = i0 + NTHREADS;
        float4 a0 = __ldcs(s4 + 2 * i0);
        float4 a1 = __ldcs(s4 + 2 * i0 + 1);
        float4 b0 = __ldcs(d4 + 2 * i0);
        float4 b1 = __ldcs(d4 + 2 * i0 + 1);
        float4 a2, a3, b2, b3;
        if (i1 < nt8) {
            a2 = __ldcs(s4 + 2 * i1);
            a3 = __ldcs(s4 + 2 * i1 + 1);
            b2 = __ldcs(d4 + 2 * i1);
            b3 = __ldcs(d4 + 2 * i1 + 1);
        }

        union { __half2 h; unsigned u; } c;
        uint4 o;
        c.h = __floats2half2_rn(a0.x, a0.y); o.x = c.u;
        c.h = __floats2half2_rn(a0.z, a0.w); o.y = c.u;
        c.h = __floats2half2_rn(a1.x, a1.y); o.z = c.u;
        c.h = __floats2half2_rn(a1.z, a1.w); o.w = c.u;
        __stcg(so + i0, o);
        c.h = __floats2half2_rn(b0.x, b0.y); o.x = c.u;
        c.h = __floats2half2_rn(b0.z, b0.w); o.y = c.u;
        c.h = __floats2half2_rn(b1.x, b1.y); o.z = c.u;
        c.h = __floats2half2_rn(b1.z, b1.w); o.w = c.u;
        __stcg(dsto + i0, o);

        if (i1 < nt8) {
            c.h = __floats2half2_rn(a2.x, a2.y); o.x = c.u;
            c.h = __floats2half2_rn(a2.z, a2.w); o.y = c.u;
            c.h = __floats2half2_rn(a3.x, a3.y); o.z = c.u;
            c.h = __floats2half2_rn(a3.z, a3.w); o.w = c.u;
            __stcg(so + i1, o);
            c.h = __floats2half2_rn(b2.x, b2.y); o.x = c.u;
            c.h = __floats2half2_rn(b2.z, b2.w); o.y = c.u;
            c.h = __floats2half2_rn(b3.x, b3.y); o.z = c.u;
            c.h = __floats2half2_rn(b3.z, b3.w); o.w = c.u;
            __stcg(dsto + i1, o);
        }
    }
    PDL_TRIGGER();
}

// ---------------------------------------------------------------------------
// K1: gather + distance + likelihood + fused stats; last block publishes
// mu / inv_std. Triggers dependents before the last-block reduce.
// ---------------------------------------------------------------------------
__global__ __launch_bounds__(TPB) void k_edge(
    const int* __restrict__ gr, int E, int Nn)
{
    const int lane  = threadIdx.x & 31;
    const int gwarp = (blockIdx.x * TPB + threadIdx.x) >> 5;
    const int half_sel = lane & 16;
    const int lane15   = lane & 15;
    const int nwarps = NTHREADS / 32;

    PDL_WAIT();    // tables must be converted

    const uint4* __restrict__ stab = (const uint4*)g_srch;
    const uint4* __restrict__ dtab = (const uint4*)g_dsth;

    double a1 = 0.0, a2 = 0.0;

    for (int base = gwarp * 32; base < E; base += nwarps * 32) {
        const int m = min(32, E - base);
        const int e = base + lane;

        int si = 0, di = 0;
        if (lane < m) {
            si = __ldcs(gr + e);
            di = __ldcs(gr + (size_t)E + e);
        }
        si = min(max(si, 0), Nn - 1);
        di = min(max(di, 0), Nn - 1);

        float acc = 0.0f;

        #pragma unroll 4
        for (int t = 0; t < 16; t++) {
            const int srcl = t | half_sel;
            const int s = __shfl_sync(0xffffffffu, si, srcl);
            const int d = __shfl_sync(0xffffffffu, di, srcl);

            uint4 av = __ldg(stab + (size_t)s * 16 + lane15);
            uint4 bv = __ldg(dtab + (size_t)d * 16 + lane15);
            const __half2* ah = (const __half2*)&av;
            const __half2* bh = (const __half2*)&bv;

            float p = 0.0f;
            #pragma unroll
            for (int i = 0; i < 4; i++) {
                float2 fa = __half22float2(ah[i]);
                float2 fb = __half22float2(bh[i]);
                float dx = fa.x - fb.x, dy = fa.y - fb.y;
                p = fmaf(dx, dx, fmaf(dy, dy, p));
            }
            #pragma unroll
            for (int o = 8; o; o >>= 1)
                p += __shfl_xor_sync(0xffffffffu, p, o);

            if (lane15 == t) acc = p;
        }

        if (lane < m) {
            float v = -__logf(fmaxf(acc, 1e-12f));
            __stcs(g_lik + e, v);
            a1 += (double)v;
            a2 += (double)v * (double)v;
        }
    }

    __shared__ double sh1[TPB], shq[TPB];
    sh1[threadIdx.x] = a1; shq[threadIdx.x] = a2;
    __syncthreads();
    for (int st = TPB / 2; st; st >>= 1) {
        if (threadIdx.x < st) {
            sh1[threadIdx.x] += sh1[threadIdx.x + st];
            shq[threadIdx.x] += shq[threadIdx.x + st];
        }
        __syncthreads();
    }
    __shared__ int s_last;
    if (threadIdx.x == 0) {
        g_p1[blockIdx.x] = sh1[0];
        g_p2[blockIdx.x] = shq[0];
        __threadfence();
        unsigned old = atomicAdd(&g_c1, 1u);
        s_last = ((old % NB) == NB - 1);       // replay-safe
    }
    __syncthreads();
    PDL_TRIGGER();   // k_post starts its independent copies now

    if (s_last) {                              // last block finalizes mu/inv_std
        double t1 = 0.0, t2 = 0.0;
        for (int i = threadIdx.x; i < NB; i += TPB) { t1 += g_p1[i]; t2 += g_p2[i]; }
        sh1[threadIdx.x] = t1; shq[threadIdx.x] = t2;
        __syncthreads();
        for (int st = TPB / 2; st; st >>= 1) {
            if (threadIdx.x < st) {
                sh1[threadIdx.x] += sh1[threadIdx.x + st];
                shq[threadIdx.x] += shq[threadIdx.x + st];
            }
            __syncthreads();
        }
        if (threadIdx.x == 0) {
            double mu  = sh1[0] / (double)E;
            double var = shq[0] / (double)E - mu * mu;
            g_mu  = (float)mu;
            g_inv = (float)rsqrt(var + 1e-5);
        }
    }
}

// ---------------------------------------------------------------------------
// K2 (fused tail): graph copies (pre-wait) + logits + sigmoid-in-registers +
// last-block inv_mean publish + co-resident spin barrier + ew from registers.
// __launch_bounds__(TPB, 8) is LOAD-BEARING: it guarantees 8 blocks/SM so all
// NB blocks are co-resident and the spin barrier cannot deadlock.
// ---------------------------------------------------------------------------
__global__ __launch_bounds__(TPB, 8) void k_post(
    const int* __restrict__ gr,
    const float* __restrict__ bw, const float* __restrict__ bb,
    float* __restrict__ out, int E)
{
    const int tid = blockIdx.x * TPB + threadIdx.x;
    const int E4  = E >> 2;

    // --- both graph rows -> float out, vectorized (independent of k_edge)
    {
        const int E2_4 = (2 * E) >> 2;
        const int4* __restrict__ gi = (const int4*)gr;
        float4* __restrict__ go = (float4*)out;
        for (int i = tid; i < E2_4; i += NTHREADS) {
            int4 v = __ldcs(gi + i);
            __stcs(go + i, make_float4((float)v.x, (float)v.y, (float)v.z, (float)v.w));
        }
        for (int i = E2_4 * 4 + tid; i < 2 * E; i += NTHREADS)
            __stcs(out + i, (float)__ldcs(gr + i));
    }

    PDL_WAIT();    // primary grid complete: g_mu / g_inv / g_lik visible

    const float mu = g_mu;
    const float wi = __ldg(bw) * g_inv;
    const float b  = __ldg(bb);

    float4* __restrict__ lik4 = (float4*)g_lik;
    float4* __restrict__ lg4 = (float4*)(out + 3LL * E);

    // --- logits stored; sigmoid kept in registers (<=2 chunks/thread here)
    float4 keep[2];
    double s = 0.0;
    int c = 0;
    for (int i = tid; i < E4; i += NTHREADS, c++) {
        float4 l = lik4[i];
        float4 g;
        g.x = fmaf(wi, l.x - mu, b); g.y = fmaf(wi, l.y - mu, b);
        g.z = fmaf(wi, l.z - mu, b); g.w = fmaf(wi, l.w - mu, b);
        __stcs(lg4 + i, g);
        float4 sg;
        sg.x = 1.0f / (1.0f + __expf(-g.x));
        sg.y = 1.0f / (1.0f + __expf(-g.y));
        sg.z = 1.0f / (1.0f + __expf(-g.z));
        sg.w = 1.0f / (1.0f + __expf(-g.w));
        if (c < 2) keep[c] = sg; else lik4[i] = sg;   // spill path for generality
        s += (double)((sg.x + sg.y) + (sg.z + sg.w));
    }
    for (int e = E4 * 4 + tid; e < E; e += NTHREADS) {   // generic tail
        float lg = fmaf(wi, g_lik[e] - mu, b);
        out[3LL * E + e] = lg;
        float sg = 1.0f / (1.0f + __expf(-lg));
        g_lik[e] = sg;
        s += (double)sg;
    }

    // --- block partial, arrival, last-block publish of inv_mean
    __shared__ double sh[TPB];
    sh[threadIdx.x] = s;
    __syncthreads();
    for (int st = TPB / 2; st; st >>= 1) {
        if (threadIdx.x < st) sh[threadIdx.x] += sh[threadIdx.x + st];
        __syncthreads();
    }
    __shared__ int s_last;
    __shared__ unsigned s_round;
    if (threadIdx.x == 0) {
        g_p3[blockIdx.x] = sh[0];
        __threadfence();
        unsigned old = atomicAdd(&g_c2, 1u);
        s_last  = ((old % NB) == NB - 1);
        s_round = old / NB;                    // replay round index
    }
    __syncthreads();

    if (s_last) {
        double t = 0.0;
        for (int i = threadIdx.x; i < NB; i += TPB) t += g_p3[i];
        sh[threadIdx.x] = t;
        __syncthreads();
        for (int st = TPB / 2; st; st >>= 1) {
            if (threadIdx.x < st) sh[threadIdx.x] += sh[threadIdx.x + st];
            __syncthreads();
        }
        if (threadIdx.x == 0) {
            g_im = (float)((double)E / sh[0]);
            __threadfence();
            atomicAdd((unsigned*)&g_done, 1u);  // round complete
        }
        __syncthreads();
    } else {
        if (threadIdx.x == 0) {
            const unsigned target = s_round + 1;
            while (g_done < target) { }
            __threadfence();
        }
        __syncthreads();
    }

    // --- ew from registers (or g_lik spill path)
    const float im = g_im;
    float4* __restrict__ ew4 = (float4*)(out + 2LL * E);
    c = 0;
    for (int i = tid; i < E4; i += NTHREADS, c++) {
        float4 v = (c < 2) ? keep[c] : lik4[i];
        v.x *= im; v.y *= im; v.z *= im; v.w *= im;
        __stcs(ew4 + i, v);
    }
    for (int e = E4 * 4 + tid; e < E; e += NTHREADS)
        out[2LL * E + e] = g_lik[e] * im;
}

// ---------------------------------------------------------------------------
template <typename... Args>
static inline void launch_pdl(void (*kern)(Args...), Args... args)
{
    cudaLaunchConfig_t cfg = {};
    cfg.gridDim  = dim3(NB, 1, 1);
    cfg.blockDim = dim3(TPB, 1, 1);
    cudaLaunchAttribute a[1];
    a[0].id = cudaLaunchAttributeProgrammaticStreamSerialization;
    a[0].val.programmaticStreamSerializationAllowed = 1;
    cfg.attrs = a;
    cfg.numAttrs = 1;
    cudaLaunchKernelEx(&cfg, kern, args...);
}

extern "C" void kernel_launch(void* const* d_in, const int* in_sizes, int n_in,
                              void* d_out, int out_size)
{
    const float* src = (const float*)d_in[0];
    const float* dst = (const float*)d_in[1];
    const int*   gr  = (const int*)d_in[2];
    const float* bw  = (const float*)d_in[3];
    const float* bb  = (const float*)d_in[4];
    float* out = (float*)d_out;

    const int E  = in_sizes[2] / 2;
    const int Nn = in_sizes[0] / DD;
    const int total = min(in_sizes[0], 100000 * DD);

    k_conv<<<NB, TPB>>>(src, dst, total);
    launch_pdl(k_edge, gr, E, Nn);
    launch_pdl(k_post, gr, bw, bb, out, E);
}

// round 16
// speedup vs baseline: 1.0530x; 1.0530x over previous
#include <cuda_runtime.h>
#include <cuda_fp16.h>
#include <math.h>

// Problem constants: N=100000, D=128, E=1600000
#define DD   128
#define EMAX 1600000
#define NB   1184          // 8 blocks/SM * 148
#define TPB  256
#define NTHREADS (NB * TPB)

#define PDL_WAIT()    asm volatile("griddepcontrol.wait;" ::: "memory")
#define PDL_TRIGGER() asm volatile("griddepcontrol.launch_dependents;" ::: "memory")

// Static device scratch (no allocations)
__device__ __half g_srch[100000 * DD];  // fp16 src table (row = 256B = 16 uint4)
__device__ __half g_dsth[100000 * DD];  // fp16 dst table
__device__ float  g_lik[EMAX];          // likelihood (k_edge -> k_logits)
__device__ double g_p1[NB], g_p2[NB], g_p3[NB];
__device__ float  g_mu, g_inv, g_im;
__device__ unsigned g_c1, g_c2;         // monotonic arrival counters (replay-safe)

// ---------------------------------------------------------------------------
// K0: fp32 -> fp16 tables. Simple grid-stride loop; __launch_bounds__(TPB,8)
// pins regs <= 32 so occupancy (not manual unrolling) hides latency.
// ---------------------------------------------------------------------------
__global__ __launch_bounds__(TPB, 8) void k_conv(
    const float* __restrict__ src, const float* __restrict__ dst, int total)
{
    const int nt8 = total >> 3;
    const float4* __restrict__ s4 = (const float4*)src;
    const float4* __restrict__ d4 = (const float4*)dst;
    uint4* __restrict__ so = (uint4*)g_srch;
    uint4* __restrict__ dsto = (uint4*)g_dsth;

    const int tid = blockIdx.x * TPB + threadIdx.x;

    for (int i = tid; i < nt8; i += NTHREADS) {
        float4 a0 = __ldcs(s4 + 2 * i);
        float4 a1 = __ldcs(s4 + 2 * i + 1);
        float4 b0 = __ldcs(d4 + 2 * i);
        float4 b1 = __ldcs(d4 + 2 * i + 1);

        union { __half2 h; unsigned u; } c;
        uint4 o;
        c.h = __floats2half2_rn(a0.x, a0.y); o.x = c.u;
        c.h = __floats2half2_rn(a0.z, a0.w); o.y = c.u;
        c.h = __floats2half2_rn(a1.x, a1.y); o.z = c.u;
        c.h = __floats2half2_rn(a1.z, a1.w); o.w = c.u;
        __stcg(so + i, o);
        c.h = __floats2half2_rn(b0.x, b0.y); o.x = c.u;
        c.h = __floats2half2_rn(b0.z, b0.w); o.y = c.u;
        c.h = __floats2half2_rn(b1.x, b1.y); o.z = c.u;
        c.h = __floats2half2_rn(b1.z, b1.w); o.w = c.u;
        __stcg(dsto + i, o);
    }
    PDL_TRIGGER();
}

// ---------------------------------------------------------------------------
// K1: gather + distance + likelihood + fused stats; last block publishes
// mu / inv_std. Triggers dependents before the last-block reduce.
// ---------------------------------------------------------------------------
__global__ __launch_bounds__(TPB) void k_edge(
    const int* __restrict__ gr, int E, int Nn)
{
    const int lane  = threadIdx.x & 31;
    const int gwarp = (blockIdx.x * TPB + threadIdx.x) >> 5;
    const int half_sel = lane & 16;
    const int lane15   = lane & 15;
    const int nwarps = NTHREADS / 32;

    PDL_WAIT();    // tables must be converted

    const uint4* __restrict__ stab = (const uint4*)g_srch;
    const uint4* __restrict__ dtab = (const uint4*)g_dsth;

    double a1 = 0.0, a2 = 0.0;

    for (int base = gwarp * 32; base < E; base += nwarps * 32) {
        const int m = min(32, E - base);
        const int e = base + lane;

        int si = 0, di = 0;
        if (lane < m) {
            si = __ldcs(gr + e);
            di = __ldcs(gr + (size_t)E + e);
        }
        si = min(max(si, 0), Nn - 1);
        di = min(max(di, 0), Nn - 1);

        float acc = 0.0f;

        #pragma unroll 4
        for (int t = 0; t < 16; t++) {
            const int srcl = t | half_sel;
            const int s = __shfl_sync(0xffffffffu, si, srcl);
            const int d = __shfl_sync(0xffffffffu, di, srcl);

            uint4 av = __ldg(stab + (size_t)s * 16 + lane15);
            uint4 bv = __ldg(dtab + (size_t)d * 16 + lane15);
            const __half2* ah = (const __half2*)&av;
            const __half2* bh = (const __half2*)&bv;

            float p = 0.0f;
            #pragma unroll
            for (int i = 0; i < 4; i++) {
                float2 fa = __half22float2(ah[i]);
                float2 fb = __half22float2(bh[i]);
                float dx = fa.x - fb.x, dy = fa.y - fb.y;
                p = fmaf(dx, dx, fmaf(dy, dy, p));
            }
            #pragma unroll
            for (int o = 8; o; o >>= 1)
                p += __shfl_xor_sync(0xffffffffu, p, o);

            if (lane15 == t) acc = p;
        }

        if (lane < m) {
            float v = -__logf(fmaxf(acc, 1e-12f));
            __stcs(g_lik + e, v);
            a1 += (double)v;
            a2 += (double)v * (double)v;
        }
    }

    __shared__ double sh1[TPB], shq[TPB];
    sh1[threadIdx.x] = a1; shq[threadIdx.x] = a2;
    __syncthreads();
    for (int st = TPB / 2; st; st >>= 1) {
        if (threadIdx.x < st) {
            sh1[threadIdx.x] += sh1[threadIdx.x + st];
            shq[threadIdx.x] += shq[threadIdx.x + st];
        }
        __syncthreads();
    }
    __shared__ int s_last;
    if (threadIdx.x == 0) {
        g_p1[blockIdx.x] = sh1[0];
        g_p2[blockIdx.x] = shq[0];
        __threadfence();
        unsigned old = atomicAdd(&g_c1, 1u);
        s_last = ((old % NB) == NB - 1);       // replay-safe
    }
    __syncthreads();
    PDL_TRIGGER();   // k_logits can start its independent copy now

    if (s_last) {                              // last block finalizes mu/inv_std
        double t1 = 0.0, t2 = 0.0;
        for (int i = threadIdx.x; i < NB; i += TPB) { t1 += g_p1[i]; t2 += g_p2[i]; }
        sh1[threadIdx.x] = t1; shq[threadIdx.x] = t2;
        __syncthreads();
        for (int st = TPB / 2; st; st >>= 1) {
            if (threadIdx.x < st) {
                sh1[threadIdx.x] += sh1[threadIdx.x + st];
                shq[threadIdx.x] += shq[threadIdx.x + st];
            }
            __syncthreads();
        }
        if (threadIdx.x == 0) {
            double mu  = sh1[0] / (double)E;
            double var = shq[0] / (double)E - mu * mu;
            g_mu  = (float)mu;
            g_inv = (float)rsqrt(var + 1e-5);
        }
    }
}

// ---------------------------------------------------------------------------
// K2: graph row0 copy (vectorized int4->float4, pre-wait: overlaps k_edge
// tail) + logits + sigmoid partial sums; last block publishes inv_mean.
// ---------------------------------------------------------------------------
__global__ __launch_bounds__(TPB) void k_logits(
    const int* __restrict__ gr,
    const float* __restrict__ bw, const float* __restrict__ bb,
    float* __restrict__ out, int E)
{
    const int tid = blockIdx.x * TPB + threadIdx.x;
    const int E4  = E >> 2;

    // graph row 0 -> float out, vectorized (independent of k_edge)
    {
        const int4* __restrict__ gi = (const int4*)gr;
        float4* __restrict__ go = (float4*)out;
        for (int i = tid; i < E4; i += NTHREADS) {
            int4 v = __ldcs(gi + i);
            __stcs(go + i, make_float4((float)v.x, (float)v.y, (float)v.z, (float)v.w));
        }
        for (int i = E4 * 4 + tid; i < E; i += NTHREADS)
            __stcs(out + i, (float)__ldcs(gr + i));
    }

    PDL_WAIT();    // g_mu / g_inv / g_lik now visible

    const float mu = g_mu;
    const float wi = __ldg(bw) * g_inv;
    const float b  = __ldg(bb);

    const float4* __restrict__ lik4 = (const float4*)g_lik;
    float4* __restrict__ lg4 = (float4*)(out + 3LL * E);

    double s = 0.0;

    for (int i = tid; i < E4; i += NTHREADS) {
        float4 l = lik4[i];
        float4 g;
        g.x = fmaf(wi, l.x - mu, b); g.y = fmaf(wi, l.y - mu, b);
        g.z = fmaf(wi, l.z - mu, b); g.w = fmaf(wi, l.w - mu, b);
        __stcs(lg4 + i, g);
        s += (double)((1.0f / (1.0f + __expf(-g.x)) + 1.0f / (1.0f + __expf(-g.y))) +
                      (1.0f / (1.0f + __expf(-g.z)) + 1.0f / (1.0f + __expf(-g.w))));
    }
    for (int e = E4 * 4 + tid; e < E; e += NTHREADS) {
        float lg = fmaf(wi, g_lik[e] - mu, b);
        out[3LL * E + e] = lg;
        s += (double)(1.0f / (1.0f + __expf(-lg)));
    }

    __shared__ double sh[TPB];
    sh[threadIdx.x] = s;
    __syncthreads();
    for (int st = TPB / 2; st; st >>= 1) {
        if (threadIdx.x < st) sh[threadIdx.x] += sh[threadIdx.x + st];
        __syncthreads();
    }
    __shared__ int s_last;
    if (threadIdx.x == 0) {
        g_p3[blockIdx.x] = sh[0];
        __threadfence();
        unsigned old = atomicAdd(&g_c2, 1u);
        s_last = ((old % NB) == NB - 1);
    }
    __syncthreads();
    PDL_TRIGGER();   // k_ew can start its independent copy now

    if (s_last) {
        double t = 0.0;
        for (int i = threadIdx.x; i < NB; i += TPB) t += g_p3[i];
        sh[threadIdx.x] = t;
        __syncthreads();
        for (int st = TPB / 2; st; st >>= 1) {
            if (threadIdx.x < st) sh[threadIdx.x] += sh[threadIdx.x + st];
            __syncthreads();
        }
        if (threadIdx.x == 0) g_im = (float)((double)E / sh[0]);
    }
}

// ---------------------------------------------------------------------------
// K3: graph row1 copy (vectorized, pre-wait) + edge weights (sigmoid
// recomputed from L2-hot logits, scaled by inv_mean).
// ---------------------------------------------------------------------------
__global__ __launch_bounds__(TPB) void k_ew(
    const int* __restrict__ gr, float* __restrict__ out, int E)
{
    const int tid = blockIdx.x * TPB + threadIdx.x;
    const int E4  = E >> 2;

    // graph row 1 -> float out, vectorized (independent of k_logits results)
    {
        const int4* __restrict__ gi = (const int4*)(gr + (size_t)E);
        float4* __restrict__ go = (float4*)(out + (size_t)E);
        for (int i = tid; i < E4; i += NTHREADS) {
            int4 v = __ldcs(gi + i);
            __stcs(go + i, make_float4((float)v.x, (float)v.y, (float)v.z, (float)v.w));
        }
        for (int i = E4 * 4 + tid; i < E; i += NTHREADS)
            __stcs(out + (size_t)E + i, (float)__ldcs(gr + (size_t)E + i));
    }

    PDL_WAIT();    // g_im and logits now visible

    const float im = g_im;
    const float4* __restrict__ lg4 = (const float4*)(out + 3LL * E);
    float4* __restrict__ ew4 = (float4*)(out + 2LL * E);

    for (int i = tid; i < E4; i += NTHREADS) {
        float4 g = __ldcs(lg4 + i);
        float4 v;
        v.x = im / (1.0f + __expf(-g.x)); v.y = im / (1.0f + __expf(-g.y));
        v.z = im / (1.0f + __expf(-g.z)); v.w = im / (1.0f + __expf(-g.w));
        __stcs(ew4 + i, v);
    }
    for (int e = E4 * 4 + tid; e < E; e += NTHREADS)
        out[2LL * E + e] = im / (1.0f + __expf(-out[3LL * E + e]));
}

// ---------------------------------------------------------------------------
template <typename... Args>
static inline void launch_pdl(void (*kern)(Args...), Args... args)
{
    cudaLaunchConfig_t cfg = {};
    cfg.gridDim  = dim3(NB, 1, 1);
    cfg.blockDim = dim3(TPB, 1, 1);
    cudaLaunchAttribute a[1];
    a[0].id = cudaLaunchAttributeProgrammaticStreamSerialization;
    a[0].val.programmaticStreamSerializationAllowed = 1;
    cfg.attrs = a;
    cfg.numAttrs = 1;
    cudaLaunchKernelEx(&cfg, kern, args...);
}

extern "C" void kernel_launch(void* const* d_in, const int* in_sizes, int n_in,
                              void* d_out, int out_size)
{
    const float* src = (const float*)d_in[0];
    const float* dst = (const float*)d_in[1];
    const int*   gr  = (const int*)d_in[2];
    const float* bw  = (const float*)d_in[3];
    const float* bb  = (const float*)d_in[4];
    float* out = (float*)d_out;

    const int E  = in_sizes[2] / 2;
    const int Nn = in_sizes[0] / DD;
    const int total = min(in_sizes[0], 100000 * DD);

    k_conv<<<NB, TPB>>>(src, dst, total);
    launch_pdl(k_edge, gr, E, Nn);
    launch_pdl(k_logits, gr, bw, bb, out, E);
    launch_pdl(k_ew, gr, out, E);
}